// round 13
// baseline (speedup 1.0000x reference)
#include <cuda_runtime.h>
#include <cuda_bf16.h>

#define V_DIM 32
#define NB 14          // N_BASIS
#define NP 496         // V*(V-1)/2
#define PSTRIDE 512    // padded params row stride: bank-conflict-free (512%32==0)
#define NW 16          // warps per block
#define NTHREADS 512
#define GRID 296       // 2 blocks/SM on 148 SMs

struct SmemLayout {
    float P[NB * PSTRIDE]; // padded staged params (28672 B)
    float red[3][NW];
};

__global__ __launch_bounds__(NTHREADS, 2)
void decor_kernel(const float* __restrict__ input,
                  const float* __restrict__ params,
                  float* __restrict__ d_out,
                  float* __restrict__ scal,
                  int n)
{
    extern __shared__ char smem_raw[];
    SmemLayout* S = reinterpret_cast<SmemLayout*>(smem_raw);

    const int tid  = threadIdx.x;
    const int warp = tid >> 5;
    const int lane = tid & 31;

    // ---- stage params (padded) once per block ----
    for (int i = tid; i < NB * NP; i += NTHREADS) {
        int r = i / NP, cc = i - r * NP;
        S->P[r * PSTRIDE + cc] = params[i];
    }
    __syncthreads();

    // ---- block 0: fused penalties ----
    if (blockIdx.x == 0) {
        float s0 = 0.f, s1 = 0.f, s2 = 0.f;
        for (int i = tid; i < NB * NP; i += NTHREADS) {
            int k = i / NP, cc = i - k * NP;
            float p0 = S->P[k * PSTRIDE + cc];
            s0 += p0 * p0;
            if (k < NB - 1) {
                float p1 = S->P[(k + 1) * PSTRIDE + cc];
                float a = p1 - p0;
                s1 += a * a;
                if (k < NB - 2) {
                    float b = S->P[(k + 2) * PSTRIDE + cc] - 2.0f * p1 + p0;
                    s2 += b * b;
                }
            }
        }
        #pragma unroll
        for (int off = 16; off > 0; off >>= 1) {
            s0 += __shfl_down_sync(0xffffffffu, s0, off);
            s1 += __shfl_down_sync(0xffffffffu, s1, off);
            s2 += __shfl_down_sync(0xffffffffu, s2, off);
        }
        if (lane == 0) { S->red[0][warp] = s2; S->red[1][warp] = s1; S->red[2][warp] = s0; }
        __syncthreads();
        if (tid < 3) {
            float t = 0.f;
            #pragma unroll
            for (int w2 = 0; w2 < NW; w2++) t += S->red[tid][w2];
            scal[tid] = t;   // [0]=second, [1]=first, [2]=param
        }
    }

    const float LOv = -15.0f, HIv = 15.0f;
    const float inv_dist = 11.0f / 30.0f;
    const float SIXTH = 1.0f / 6.0f;

    float* lm = d_out + (size_t)n * V_DIM;
    const int row_stride = gridDim.x * NW;
    const int cb = (lane & 7) << 2;      // this lane's column quad base
    const int vh = lane >> 3;            // v offset within each iteration

    for (int row = blockIdx.x * NW + warp; row < n; row += row_stride) {

        // input row: lane owns column `lane` (coalesced LDG)
        float xi = input[(size_t)row * V_DIM + lane];

        // gather this lane's 4 columns of x; derive basis in-lane (4 columns only)
        float xq[4];
        float B0[4], B1[4], B2[4], B3[4];
        int   jb[4];                     // j0(c)*PSTRIDE + c
        #pragma unroll
        for (int q = 0; q < 4; q++) {
            int c = cb + q;
            float xc = __shfl_sync(0xffffffffu, xi, c);
            xq[q] = xc;
            float s  = (fminf(fmaxf(xc, LOv), HIv - 1e-6f) - LOv) * inv_dist;
            int j0 = min((int)s, 10);
            float u  = s - (float)j0;
            float um = 1.0f - u;
            float u2 = u * u;
            float u3 = u2 * u;
            float b0 = um * um * um * SIXTH;
            float b3 = u3 * SIXTH;
            float b1 = fmaf(0.5f, u3, 2.0f / 3.0f) - u2;
            B0[q] = b0; B1[q] = b1; B3[q] = b3;
            B2[q] = 1.0f - b0 - b1 - b3;
            jb[q] = j0 * PSTRIDE + c;
        }

        // 8 iterations: compute the quad (v, cb..cb+3) in registers,
        // STG.128 directly, fused out = lm @ x. No smem scratch, no syncs.
        float4* lmrow = reinterpret_cast<float4*>(lm + (size_t)row * V_DIM * V_DIM);
        #pragma unroll
        for (int i = 0; i < 8; i++) {
            int v  = vh + 4 * i;
            int pb = (v * (v - 1)) >> 1;
            float vals[4];
            #pragma unroll
            for (int q = 0; q < 4; q++) {
                int c = cb + q;
                float val;
                if (c < v) {
                    // lam(v,c) = sum_j B_j(c) * P[j0(c)+j, pb(v)+c]
                    const float* Pp = S->P + jb[q] + pb;
                    float l = B0[q] * Pp[0];
                    l = fmaf(B1[q], Pp[PSTRIDE],     l);
                    l = fmaf(B2[q], Pp[2 * PSTRIDE], l);
                    l = fmaf(B3[q], Pp[3 * PSTRIDE], l);
                    val = l;
                } else {
                    val = (c == v) ? 1.0f : 0.0f;
                }
                vals[q] = val;
            }
            __stcs(&lmrow[lane + 32 * i],
                   make_float4(vals[0], vals[1], vals[2], vals[3]));

            // out[v] = dot(lm_row_v, x): width-8 reduction over the 8 lanes of v
            float dv = vals[0] * xq[0];
            dv = fmaf(vals[1], xq[1], dv);
            dv = fmaf(vals[2], xq[2], dv);
            dv = fmaf(vals[3], xq[3], dv);
            dv += __shfl_xor_sync(0xffffffffu, dv, 4, 8);
            dv += __shfl_xor_sync(0xffffffffu, dv, 2, 8);
            dv += __shfl_xor_sync(0xffffffffu, dv, 1, 8);
            if ((lane & 7) == 0)
                d_out[(size_t)row * V_DIM + v] = dv;
        }
    }
}

extern "C" void kernel_launch(void* const* d_in, const int* in_sizes, int n_in,
                              void* d_out, int out_size)
{
    const float* input  = (const float*)d_in[0];
    // d_in[1] = log_d (unused by the reference's outputs)
    const float* params = (const float*)d_in[2];
    float* outp = (float*)d_out;
    int n = in_sizes[0] / V_DIM;

    float* scal = outp + (size_t)n * V_DIM + (size_t)n * V_DIM * V_DIM;

    size_t smem = sizeof(SmemLayout);
    cudaFuncSetAttribute(decor_kernel, cudaFuncAttributeMaxDynamicSharedMemorySize, (int)smem);

    decor_kernel<<<GRID, NTHREADS, smem>>>(input, params, outp, scal, n);
}

// round 14
// speedup vs baseline: 1.0786x; 1.0786x over previous
#include <cuda_runtime.h>
#include <cuda_bf16.h>

#define V_DIM 32
#define NB 14          // N_BASIS
#define NP 496         // V*(V-1)/2
#define PSTRIDE 512    // padded params row stride: bank-conflict-free (512%32==0)
#define NW 16          // warps per block
#define NTHREADS 512
#define GRID 296       // 2 blocks/SM on 148 SMs

struct WarpScratch {
    float Ls[512];         // lam values, p-linear; [496..511] = write-only pad
};

struct SmemLayout {
    float P[NB * PSTRIDE]; // padded staged params (28672 B)
    WarpScratch w[NW];
    float red[3][NW];
};

__global__ __launch_bounds__(NTHREADS, 2)
void decor_kernel(const float* __restrict__ input,
                  const float* __restrict__ params,
                  float* __restrict__ d_out,
                  float* __restrict__ scal,
                  int n)
{
    extern __shared__ char smem_raw[];
    SmemLayout* S = reinterpret_cast<SmemLayout*>(smem_raw);

    const int tid  = threadIdx.x;
    const int warp = tid >> 5;
    const int lane = tid & 31;

    // ---- stage params (padded) once per block, vectorized float4 ----
    // NP = 496 = 124 float4 per basis row; cc stays a multiple of 4, so both
    // source (params + 4i) and dest (P[r*512+cc]) are 16B-aligned.
    {
        const float4* p4 = reinterpret_cast<const float4*>(params);
        for (int i = tid; i < NB * (NP / 4); i += NTHREADS) {
            int i4 = i << 2;
            int r  = i4 / NP;
            int cc = i4 - r * NP;
            *reinterpret_cast<float4*>(&S->P[r * PSTRIDE + cc]) = p4[i];
        }
    }

    WarpScratch* W = &S->w[warp];

    // row-independent pair geometry: p = lane+32*i -> pb = v(v-1)/2
    int PB[16];
    #pragma unroll
    for (int i = 0; i < 16; i++) {
        int p = lane + 32 * i;
        int v = (int)((1.0f + sqrtf(8.0f * (float)p + 1.0f)) * 0.5f);
        while (v * (v + 1) / 2 <= p) v++;
        while (v * (v - 1) / 2 > p) v--;
        PB[i] = v * (v - 1) / 2;
    }
    __syncthreads();

    // ---- block 0: fused penalties ----
    if (blockIdx.x == 0) {
        float s0 = 0.f, s1 = 0.f, s2 = 0.f;
        for (int i = tid; i < NB * NP; i += NTHREADS) {
            int k = i / NP, cc = i - k * NP;
            float p0 = S->P[k * PSTRIDE + cc];
            s0 += p0 * p0;
            if (k < NB - 1) {
                float p1 = S->P[(k + 1) * PSTRIDE + cc];
                float a = p1 - p0;
                s1 += a * a;
                if (k < NB - 2) {
                    float b = S->P[(k + 2) * PSTRIDE + cc] - 2.0f * p1 + p0;
                    s2 += b * b;
                }
            }
        }
        #pragma unroll
        for (int off = 16; off > 0; off >>= 1) {
            s0 += __shfl_down_sync(0xffffffffu, s0, off);
            s1 += __shfl_down_sync(0xffffffffu, s1, off);
            s2 += __shfl_down_sync(0xffffffffu, s2, off);
        }
        if (lane == 0) { S->red[0][warp] = s2; S->red[1][warp] = s1; S->red[2][warp] = s0; }
        __syncthreads();
        if (tid < 3) {
            float t = 0.f;
            #pragma unroll
            for (int w2 = 0; w2 < NW; w2++) t += S->red[tid][w2];
            scal[tid] = t;   // [0]=second, [1]=first, [2]=param
        }
    }

    const float LOv = -15.0f, HIv = 15.0f;
    const float inv_dist = 11.0f / 30.0f;
    const float SIXTH = 1.0f / 6.0f;

    float* lm = d_out + (size_t)n * V_DIM;
    const int row_stride = gridDim.x * NW;
    const int cb = (lane & 7) << 2;

    for (int row = blockIdx.x * NW + warp; row < n; row += row_stride) {

        // input row: lane owns column `lane` (coalesced LDG)
        float xi = input[(size_t)row * V_DIM + lane];

        // pre-clamped, pre-scaled spline coordinate for this lane's column
        float s_lane = (fminf(fmaxf(xi, LOv), HIv - 1e-6f) - LOv) * inv_dist;

        // x segment for the fused dot: lane-constant across store iters
        float xq0 = __shfl_sync(0xffffffffu, xi, cb);
        float xq1 = __shfl_sync(0xffffffffu, xi, cb + 1);
        float xq2 = __shfl_sync(0xffffffffu, xi, cb + 2);
        float xq3 = __shfl_sync(0xffffffffu, xi, cb + 3);

        // lam: 1 shuffle of s + in-lane basis recompute; P loads conflict-free;
        // Ls STS p-linear (bank == lane, conflict-free), unconditional via pad
        #pragma unroll
        for (int i = 0; i < 16; i++) {
            int p = lane + 32 * i;
            int c = (p - PB[i]) & 31;
            float s  = __shfl_sync(0xffffffffu, s_lane, c);
            int j0 = min((int)s, 10);
            float u  = s - (float)j0;
            float um = 1.0f - u;
            float u2 = u * u;
            float u3 = u2 * u;
            float b0 = um * um * um * SIXTH;
            float b3 = u3 * SIXTH;
            float b1 = fmaf(0.5f, u3, 2.0f / 3.0f) - u2;
            float b2 = 1.0f - b0 - b1 - b3;
            const float* Pp = S->P + j0 * PSTRIDE + p;
            float l = b0 * Pp[0];
            l = fmaf(b1, Pp[PSTRIDE],     l);
            l = fmaf(b2, Pp[2 * PSTRIDE], l);
            l = fmaf(b3, Pp[3 * PSTRIDE], l);
            W->Ls[p] = l;            // p>=NP lands in pad, never read
        }
        __syncwarp();

        // lm store (STG.128, coalesced) with fused out = lm @ x
        float4* lmrow = reinterpret_cast<float4*>(lm + (size_t)row * V_DIM * V_DIM);
        #pragma unroll
        for (int i = 0; i < 8; i++) {
            int t4 = lane + 32 * i;          // == v*8 + cb/4
            int v  = t4 >> 3;
            int pb = (v * (v - 1)) >> 1;
            float vals[4];
            #pragma unroll
            for (int q = 0; q < 4; q++) {
                int c = cb + q;
                float val = 0.0f;
                if (c < v)       val = W->Ls[pb + c];
                else if (c == v) val = 1.0f;
                vals[q] = val;
            }
            __stcs(&lmrow[t4], make_float4(vals[0], vals[1], vals[2], vals[3]));

            float dv = vals[0] * xq0;
            dv = fmaf(vals[1], xq1, dv);
            dv = fmaf(vals[2], xq2, dv);
            dv = fmaf(vals[3], xq3, dv);
            dv += __shfl_xor_sync(0xffffffffu, dv, 4, 8);
            dv += __shfl_xor_sync(0xffffffffu, dv, 2, 8);
            dv += __shfl_xor_sync(0xffffffffu, dv, 1, 8);
            // lanes 0,8,16,24 hold out[v] -> direct store
            if ((lane & 7) == 0)
                d_out[(size_t)row * V_DIM + v] = dv;
        }
        __syncwarp();   // Ls reads complete before next row's STS
    }
}

extern "C" void kernel_launch(void* const* d_in, const int* in_sizes, int n_in,
                              void* d_out, int out_size)
{
    const float* input  = (const float*)d_in[0];
    // d_in[1] = log_d (unused by the reference's outputs)
    const float* params = (const float*)d_in[2];
    float* outp = (float*)d_out;
    int n = in_sizes[0] / V_DIM;

    float* scal = outp + (size_t)n * V_DIM + (size_t)n * V_DIM * V_DIM;

    size_t smem = sizeof(SmemLayout);
    cudaFuncSetAttribute(decor_kernel, cudaFuncAttributeMaxDynamicSharedMemorySize, (int)smem);

    decor_kernel<<<GRID, NTHREADS, smem>>>(input, params, outp, scal, n);
}